// round 10
// baseline (speedup 1.0000x reference)
#include <cuda_runtime.h>
#include <cuda_bf16.h>
#include <cstdint>

// Problem dims
#define Bsz   128
#define Tsz   512
#define INsz  128
#define Hsz   1024
#define G3sz  3072
#define PREDsz 96
#define MR    (Tsz*Bsz)        // 65536 rows
#define BH    (Bsz*Hsz)        // 131072

// Scan kernel config: 128 persistent CTAs, 8 hidden units each, 16 warps (split-K 2)
#define NCTA  128
#define UPC   8                // units per CTA
#define GR    (3*UPC)          // gate rows per CTA = 24
#define WST2  516              // Wp row stride in float2 (conflict-free LDS.64)
#define GS    26               // Gs row stride (floats)
#define CH    32               // staging chunk columns (= 4 producer CTAs)
#define NCH   16               // chunks per K-half (512/32)
#define HST2  36               // staging row stride: 4g+tg distinct mod 32
#define WBUF  (16*HST2)        // 576 floats: one 16-row staging buffer
// SMEM map (floats): Wp | bias | Gs[2] | Hb[16 warps][2 bufs]
#define OFF_BH   (GR*WST2*2)                  // 24768
#define OFF_GS   (OFF_BH + 32)                // 24800
#define OFF_HB   (OFF_GS + 2*Bsz*GS)          // 31456
#define SCAN_SMEM_FLOATS (OFF_HB + 16*2*WBUF) // 49888
#define SCAN_SMEM_BYTES  (SCAN_SMEM_FLOATS*4) // 199552 B

#define NGRP  32               // producer groups (4 CTAs each)
#define BARSTRIDE 32           // 128B between counters

// ---------------- device scratch (allocation-free rule) ----------------
__device__ float g_xi [(size_t)MR*G3sz];   // [T,B,3H] input-side gate projections
__device__ float g_hsA[(size_t)MR*Hsz];    // [T,B,H] hidden sequence buffer A
__device__ float g_hsB[(size_t)MR*Hsz];    // [T,B,H] hidden sequence buffer B
__device__ unsigned g_grp[NGRP*BARSTRIDE]; // per-group step counters (reset per scan)

// ---------------- helpers ----------------
__device__ __forceinline__ unsigned tf32u(float f){
    unsigned u; asm("cvt.rna.tf32.f32 %0, %1;" : "=r"(u) : "f"(f));
    return u;
}
__device__ __forceinline__ float tf32f(float f){ return __uint_as_float(tf32u(f)); }

__device__ __forceinline__ void mma8(float* d, const unsigned* a, unsigned b0, unsigned b1){
    asm volatile("mma.sync.aligned.m16n8k8.row.col.f32.tf32.tf32.f32 "
        "{%0,%1,%2,%3},{%4,%5,%6,%7},{%8,%9},{%0,%1,%2,%3};"
        : "+f"(d[0]),"+f"(d[1]),"+f"(d[2]),"+f"(d[3])
        : "r"(a[0]),"r"(a[1]),"r"(a[2]),"r"(a[3]),"r"(b0),"r"(b1));
}

__device__ __forceinline__ float fast_sigmoid(float x){
    return 1.f/(1.f + __expf(-x));
}
__device__ __forceinline__ float fast_tanh(float x){
    float ax = fabsf(x);
    float e  = __expf(2.f*ax);
    float th = 1.f - 2.f/(e + 1.f);
    return copysignf(th, x);
}

// warp-scope wait: producers of group gidx have finished step t-1 (counter >= 4t)
__device__ __forceinline__ void wait_grp(int gidx, unsigned target){
    if ((threadIdx.x & 31) == 0){
        while ((int)(*(volatile unsigned*)&g_grp[gidx*BARSTRIDE] - target) < 0)
            __nanosleep(32);
        __threadfence();
    }
    __syncwarp();
}

// ---------------- 0) reset group counters (before each scan) ----------------
__global__ void k_reset(){
    if (threadIdx.x < NGRP) g_grp[threadIdx.x*BARSTRIDE] = 0u;
}

// ---------------- 1) XI = A @ W^T + bias  (tf32 mma, 128x128 tiles) ----------------
__global__ void __launch_bounds__(256) k_gemm(const float* __restrict__ ext, int sel,
        const float* __restrict__ W, const float* __restrict__ bias,
        int K, int perm)
{
    __shared__ float As[2][128][20];
    __shared__ float Bs[2][128][20];

    const float* A = ext ? ext : (sel==1 ? g_hsA : g_hsB);

    const int tid = threadIdx.x;
    const int lane = tid&31, wid = tid>>5;
    const int g = lane>>2, tg = lane&3;
    const int wm = wid&3, wn = wid>>2;           // 4 x 2 warps, warp tile 32x64
    const int n0 = blockIdx.x*128, m0 = blockIdx.y*128;
    const int r0 = tid>>2, q0 = tid&3;

    int ra = m0 + r0, rb = m0 + r0 + 64;
    const float* Arow0 = (perm ? A + (((size_t)(ra&(Bsz-1)))*Tsz + (ra>>7))*K
                               : A + (size_t)ra*K) + q0*4;
    const float* Arow1 = (perm ? A + (((size_t)(rb&(Bsz-1)))*Tsz + (rb>>7))*K
                               : A + (size_t)rb*K) + q0*4;
    const float* Wrow0 = W + (size_t)(n0+r0   )*K + q0*4;
    const float* Wrow1 = W + (size_t)(n0+r0+64)*K + q0*4;

    float C[2][8][4] = {};

    {   // prologue: tile 0 -> buffer 0
        float4 a0=*(const float4*)Arow0, a1=*(const float4*)Arow1;
        float4 b0=*(const float4*)Wrow0, b1=*(const float4*)Wrow1;
        float* p;
        p=&As[0][r0   ][q0*4]; p[0]=tf32f(a0.x);p[1]=tf32f(a0.y);p[2]=tf32f(a0.z);p[3]=tf32f(a0.w);
        p=&As[0][r0+64][q0*4]; p[0]=tf32f(a1.x);p[1]=tf32f(a1.y);p[2]=tf32f(a1.z);p[3]=tf32f(a1.w);
        p=&Bs[0][r0   ][q0*4]; p[0]=tf32f(b0.x);p[1]=tf32f(b0.y);p[2]=tf32f(b0.z);p[3]=tf32f(b0.w);
        p=&Bs[0][r0+64][q0*4]; p[0]=tf32f(b1.x);p[1]=tf32f(b1.y);p[2]=tf32f(b1.z);p[3]=tf32f(b1.w);
    }
    __syncthreads();

    const int nkb = K>>4;
    float4 na0,na1,nb0,nb1;
    for (int kb=0; kb<nkb; ++kb){
        if (kb+1<nkb){
            int k0=(kb+1)<<4;
            na0=*(const float4*)(Arow0+k0); na1=*(const float4*)(Arow1+k0);
            nb0=*(const float4*)(Wrow0+k0); nb1=*(const float4*)(Wrow1+k0);
        }
        const int cur = kb&1;
        #pragma unroll
        for (int ks=0; ks<2; ++ks){
            const int kk = ks*8;
            unsigned a[2][4];
            #pragma unroll
            for (int mt=0; mt<2; ++mt){
                int row = wm*32+mt*16;
                a[mt][0]=__float_as_uint(As[cur][row+g  ][kk+tg  ]);
                a[mt][1]=__float_as_uint(As[cur][row+g+8][kk+tg  ]);
                a[mt][2]=__float_as_uint(As[cur][row+g  ][kk+tg+4]);
                a[mt][3]=__float_as_uint(As[cur][row+g+8][kk+tg+4]);
            }
            #pragma unroll
            for (int nt=0; nt<8; ++nt){
                int col = wn*64+nt*8+g;
                unsigned b0=__float_as_uint(Bs[cur][col][kk+tg  ]);
                unsigned b1=__float_as_uint(Bs[cur][col][kk+tg+4]);
                mma8(C[0][nt], a[0], b0, b1);
                mma8(C[1][nt], a[1], b0, b1);
            }
        }
        if (kb+1<nkb){
            const int nb=(kb+1)&1;
            float* p;
            p=&As[nb][r0   ][q0*4]; p[0]=tf32f(na0.x);p[1]=tf32f(na0.y);p[2]=tf32f(na0.z);p[3]=tf32f(na0.w);
            p=&As[nb][r0+64][q0*4]; p[0]=tf32f(na1.x);p[1]=tf32f(na1.y);p[2]=tf32f(na1.z);p[3]=tf32f(na1.w);
            p=&Bs[nb][r0   ][q0*4]; p[0]=tf32f(nb0.x);p[1]=tf32f(nb0.y);p[2]=tf32f(nb0.z);p[3]=tf32f(nb0.w);
            p=&Bs[nb][r0+64][q0*4]; p[0]=tf32f(nb1.x);p[1]=tf32f(nb1.y);p[2]=tf32f(nb1.z);p[3]=tf32f(nb1.w);
            __syncthreads();
        }
    }

    #pragma unroll
    for (int mt=0; mt<2; ++mt){
        #pragma unroll
        for (int nt=0; nt<8; ++nt){
            int row = m0 + wm*32 + mt*16 + g;
            int col = n0 + wn*64 + nt*8 + 2*tg;
            float bb0 = bias[col], bb1 = bias[col+1];
            float2 v;
            v.x = C[mt][nt][0]+bb0; v.y = C[mt][nt][1]+bb1;
            *(float2*)&g_xi[(size_t)row*G3sz+col] = v;
            v.x = C[mt][nt][2]+bb0; v.y = C[mt][nt][3]+bb1;
            *(float2*)&g_xi[(size_t)(row+8)*G3sz+col] = v;
        }
    }
}

// ---------------- 2) persistent GRU scan v6: dataflow flags, no grid barrier ----------------
__device__ __forceinline__ void stage2(const float* __restrict__ hb, int m0, int kg0,
                                       float* buf, int lane){
    #pragma unroll
    for (int j=0;j<4;++j){
        int idx = lane + j*32;          // 0..127 : 16 rows x 8 segs(16B)
        int row = idx>>3, c4 = idx&7;
        const float* src = hb + (size_t)(m0+row)*Hsz + kg0 + c4*4;
        unsigned dst = (unsigned)__cvta_generic_to_shared(buf + row*HST2 + c4*4);
        asm volatile("cp.async.cg.shared.global [%0], [%1], 16;" :: "r"(dst), "l"(src));
    }
    asm volatile("cp.async.commit_group;" ::: "memory");
}

__global__ void __launch_bounds__(512) k_scan(const float* __restrict__ whh,
        const float* __restrict__ bhh, int sel)
{
    extern __shared__ float sm[];
    float2* Wp = (float2*)sm;              // [GR][WST2] fragment-paired tf32 w_hh
    float*  bh = sm + OFF_BH;              // [GR] biases
    float*  Gs = sm + OFF_GS;              // [2][128][GS] split-K partial gates
    float*  Hb = sm + OFF_HB;              // [16][2][WBUF] per-warp staging rings

    float* hs = (sel==1) ? g_hsA : g_hsB;
    const float* xi = g_xi;

    const int tid = threadIdx.x, bx = blockIdx.x;
    const int lane = tid&31, wid = tid>>5;
    const int g = lane>>2, tg = lane&3;
    const int kh = wid&1, mg = wid>>1;     // K-half, m-group
    const int m0 = mg*16;
    const int kbase = kh*512;
    const int grp0  = kh*16;               // first producer group for this K-half
    float* mybuf = Hb + wid*(2*WBUF);
    float* Gmy   = Gs + kh*(Bsz*GS);

    // prologue: fragment-paired tf32 weights (pair = k elems {kk+tg, kk+tg+4})
    for (int idx = tid; idx < GR*512; idx += 512){
        int r = idx>>9, p = idx&511;
        int k0 = (p>>2)<<3, tp = p&3;
        int gt = r>>3, u = r&7;
        const float* w = whh + ((size_t)(gt*Hsz + bx*UPC + u))*Hsz;
        Wp[r*WST2 + (p>>2)*4 + tp] = make_float2(tf32f(w[k0+tp]), tf32f(w[k0+tp+4]));
    }
    if (tid < GR){ int gt=tid>>3, u=tid&7; bh[tid] = bhh[gt*Hsz + bx*UPC + u]; }
    __syncthreads();

    const int eu = tid&7, eb0 = (tid>>3)*2;   // epilogue: unit, 2 batch rows
    const int ucol = bx*UPC + eu;
    float hprev[2] = {0.f, 0.f};              // register-carried own h_old

    for (int t=0; t<Tsz; ++t){
        const float* hb = hs + (size_t)(t-1)*BH;   // deref'd only when t>0
        const unsigned tgt = 4u*(unsigned)t;       // producers done step t-1

        // prefetch epilogue xi inputs (latency hides under mma phase)
        float pxr[2], pxz[2], pxn[2];
        #pragma unroll
        for (int i=0;i<2;++i){
            int b = eb0 + i;
            const float* xb = xi + ((size_t)t*Bsz + b)*G3sz + bx*UPC + eu;
            pxr[i]=xb[0]; pxz[i]=xb[Hsz]; pxn[i]=xb[2*Hsz];
        }

        if (t>0){
            float C[3][4] = {};
            wait_grp(grp0, tgt);
            stage2(hb, m0, kbase, mybuf, lane);
            for (int c=0; c<NCH; ++c){
                if (c+1 < NCH){
                    wait_grp(grp0+c+1, tgt);
                    stage2(hb, m0, kbase + (c+1)*CH, mybuf + ((c+1)&1)*WBUF, lane);
                    asm volatile("cp.async.wait_group 1;" ::: "memory");
                } else {
                    asm volatile("cp.async.wait_group 0;" ::: "memory");
                }
                __syncwarp();
                const float* war = mybuf + (c&1)*WBUF + g*HST2 + tg;
                const int kp0 = ((kbase + c*CH)>>3)*4 + tg;
                #pragma unroll
                for (int kk=0; kk<CH; kk+=8){
                    unsigned a[4];
                    a[0]=tf32u(war[kk]);      a[1]=tf32u(war[8*HST2+kk]);
                    a[2]=tf32u(war[kk+4]);    a[3]=tf32u(war[8*HST2+kk+4]);
                    const int kp = kp0 + (kk>>3)*4;
                    #pragma unroll
                    for (int nt=0; nt<3; ++nt){
                        float2 bp = Wp[(nt*8+g)*WST2 + kp];
                        mma8(C[nt], a, __float_as_uint(bp.x), __float_as_uint(bp.y));
                    }
                }
            }
            #pragma unroll
            for (int nt=0; nt<3; ++nt){
                int row = m0+g, col = nt*8+2*tg;
                *(float2*)&Gmy[row*GS+col]     = make_float2(C[nt][0], C[nt][1]);
                *(float2*)&Gmy[(row+8)*GS+col] = make_float2(C[nt][2], C[nt][3]);
            }
        }
        __syncthreads();

        // epilogue: 2 (b,u) pairs per thread; sum the two split-K partials
        float br = bh[eu], bz = bh[UPC+eu], bn = bh[2*UPC+eu];
        #pragma unroll
        for (int i=0; i<2; ++i){
            int b = eb0 + i;
            float Gr=0.f, Gz=0.f, Gn=0.f;
            if (t>0){
                Gr = Gs[b*GS+eu]       + Gs[Bsz*GS + b*GS+eu];
                Gz = Gs[b*GS+UPC+eu]   + Gs[Bsz*GS + b*GS+UPC+eu];
                Gn = Gs[b*GS+2*UPC+eu] + Gs[Bsz*GS + b*GS+2*UPC+eu];
            }
            float r  = fast_sigmoid(pxr[i] + Gr + br);
            float z  = fast_sigmoid(pxz[i] + Gz + bz);
            float nn = fast_tanh(pxn[i] + r*(Gn + bn));
            float hn = (1.f - z)*nn + z*hprev[i];
            hprev[i] = hn;
            hs[((size_t)t*Bsz + b)*Hsz + ucol] = hn;
        }

        // publish: this CTA finished step t (makes h[t] visible to consumers)
        __threadfence();
        __syncthreads();
        if (tid==0 && t < Tsz-1) atomicAdd(&g_grp[(bx>>2)*BARSTRIDE], 1u);
    }
}

// ---------------- 3) FC: out[b][p] = h_last[b] . fc_w[p] + fc_b[p] ----------------
__global__ void k_fc(const float* __restrict__ fw, const float* __restrict__ fb,
                     float* __restrict__ out)
{
    __shared__ float w[Hsz];
    const int p = blockIdx.x, b = threadIdx.x;
    for (int k=b; k<Hsz; k+=Bsz) w[k] = fw[(size_t)p*Hsz + k];
    __syncthreads();
    const float* h = g_hsA + ((size_t)(Tsz-1)*Bsz + b)*Hsz;
    float s = 0.f;
    #pragma unroll 8
    for (int k=0; k<Hsz; ++k) s += h[k]*w[k];
    out[b*PREDsz + p] = s + fb[p];
}

// ---------------- launch ----------------
extern "C" void kernel_launch(void* const* d_in, const int* in_sizes, int n_in,
                              void* d_out, int out_size)
{
    const float* x    = (const float*)d_in[0];
    const float* wih0 = (const float*)d_in[1];
    const float* whh0 = (const float*)d_in[2];
    const float* bih0 = (const float*)d_in[3];
    const float* bhh0 = (const float*)d_in[4];
    const float* wih1 = (const float*)d_in[5];
    const float* whh1 = (const float*)d_in[6];
    const float* bih1 = (const float*)d_in[7];
    const float* bhh1 = (const float*)d_in[8];
    const float* wih2 = (const float*)d_in[9];
    const float* whh2 = (const float*)d_in[10];
    const float* bih2 = (const float*)d_in[11];
    const float* bhh2 = (const float*)d_in[12];
    const float* fcw  = (const float*)d_in[13];
    const float* fcb  = (const float*)d_in[14];
    float* out = (float*)d_out;

    cudaFuncSetAttribute(k_scan, cudaFuncAttributeMaxDynamicSharedMemorySize, SCAN_SMEM_BYTES);

    dim3 gg(G3sz/128, MR/128);   // n fastest for L2 reuse

    // layer 0 (input x, permuted [B,T,IN] -> row t*B+b)
    k_gemm<<<gg, 256>>>(x, 0, wih0, bih0, INsz, 1);
    k_reset<<<1, 32>>>();
    k_scan<<<NCTA, 512, SCAN_SMEM_BYTES>>>(whh0, bhh0, 1);
    // layer 1
    k_gemm<<<gg, 256>>>(nullptr, 1, wih1, bih1, Hsz, 0);
    k_reset<<<1, 32>>>();
    k_scan<<<NCTA, 512, SCAN_SMEM_BYTES>>>(whh1, bhh1, 2);
    // layer 2
    k_gemm<<<gg, 256>>>(nullptr, 2, wih2, bih2, Hsz, 0);
    k_reset<<<1, 32>>>();
    k_scan<<<NCTA, 512, SCAN_SMEM_BYTES>>>(whh2, bhh2, 1);
    // head
    k_fc<<<PREDsz, Bsz>>>(fcw, fcb, out);
}

// round 11
// speedup vs baseline: 1.5116x; 1.5116x over previous
#include <cuda_runtime.h>
#include <cuda_bf16.h>
#include <cstdint>

// Problem dims
#define Bsz   128
#define Tsz   512
#define INsz  128
#define Hsz   1024
#define G3sz  3072
#define PREDsz 96
#define MR    (Tsz*Bsz)        // 65536 rows
#define BH    (Bsz*Hsz)        // 131072

// Scan kernel config: 128 persistent CTAs, 8 units each, 32 warps (split-K 4 x 8 m-groups)
#define NCTA  128
#define UPC   8                // units per CTA
#define GR    (3*UPC)          // gate rows per CTA = 24
#define WST2  516              // Wp row stride in float2 (conflict-free LDS.64)
#define GS    26               // Gs row stride (floats)
#define CH    16               // staging chunk columns
#define NCH   16               // chunks per K-quarter (256/16)
#define HST2  20               // staging row stride (floats): 20g+tg distinct mod 32
#define WBUF  (16*HST2)        // 320 floats: one 16-row staging buffer
// SMEM map (floats): Wp | bias | Gs[2] | Hb[32 warps][2 bufs]
#define OFF_BH   (GR*WST2*2)                  // 24768
#define OFF_GS   (OFF_BH + 32)                // 24800
#define OFF_HB   (OFF_GS + 2*Bsz*GS)          // 31456
#define SCAN_SMEM_FLOATS (OFF_HB + 32*2*WBUF) // 51936
#define SCAN_SMEM_BYTES  (SCAN_SMEM_FLOATS*4) // 207744 B

// ---------------- device scratch (allocation-free rule) ----------------
__device__ float g_xi [(size_t)MR*G3sz];   // [T,B,3H] input-side gate projections
__device__ float g_hsA[(size_t)MR*Hsz];    // [T,B,H] hidden sequence buffer A
__device__ float g_hsB[(size_t)MR*Hsz];    // [T,B,H] hidden sequence buffer B
__device__ unsigned g_bar_cnt = 0;
__device__ unsigned g_bar_gen = 0;

// ---------------- helpers ----------------
__device__ __forceinline__ unsigned tf32u(float f){
    unsigned u; asm("cvt.rna.tf32.f32 %0, %1;" : "=r"(u) : "f"(f));
    return u;
}
__device__ __forceinline__ float tf32f(float f){ return __uint_as_float(tf32u(f)); }

__device__ __forceinline__ void mma8(float* d, const unsigned* a, unsigned b0, unsigned b1){
    asm volatile("mma.sync.aligned.m16n8k8.row.col.f32.tf32.tf32.f32 "
        "{%0,%1,%2,%3},{%4,%5,%6,%7},{%8,%9},{%0,%1,%2,%3};"
        : "+f"(d[0]),"+f"(d[1]),"+f"(d[2]),"+f"(d[3])
        : "r"(a[0]),"r"(a[1]),"r"(a[2]),"r"(a[3]),"r"(b0),"r"(b1));
}

__device__ __forceinline__ float fast_sigmoid(float x){
    return 1.f/(1.f + __expf(-x));
}
__device__ __forceinline__ float fast_tanh(float x){
    float ax = fabsf(x);
    float e  = __expf(2.f*ax);
    float th = 1.f - 2.f/(e + 1.f);
    return copysignf(th, x);
}

// software grid barrier (round-7 proven single-address ticket barrier)
__device__ __forceinline__ void grid_barrier(){
    __syncthreads();
    if (threadIdx.x == 0){
        unsigned gen = atomicAdd(&g_bar_gen, 0u);
        unsigned t   = atomicAdd(&g_bar_cnt, 1u);
        if (t == NCTA-1){
            atomicExch(&g_bar_cnt, 0u);
            __threadfence();
            atomicAdd(&g_bar_gen, 1u);
        } else {
            while (atomicAdd(&g_bar_gen, 0u) == gen) { __nanosleep(32); }
        }
        __threadfence();
    }
    __syncthreads();
}

// ---------------- 1) XI = A @ W^T + bias  (tf32 mma, 128x128 tiles) ----------------
__global__ void __launch_bounds__(256) k_gemm(const float* __restrict__ ext, int sel,
        const float* __restrict__ W, const float* __restrict__ bias,
        int K, int perm)
{
    __shared__ float As[2][128][20];
    __shared__ float Bs[2][128][20];

    const float* A = ext ? ext : (sel==1 ? g_hsA : g_hsB);

    const int tid = threadIdx.x;
    const int lane = tid&31, wid = tid>>5;
    const int g = lane>>2, tg = lane&3;
    const int wm = wid&3, wn = wid>>2;           // 4 x 2 warps, warp tile 32x64
    const int n0 = blockIdx.x*128, m0 = blockIdx.y*128;
    const int r0 = tid>>2, q0 = tid&3;

    int ra = m0 + r0, rb = m0 + r0 + 64;
    const float* Arow0 = (perm ? A + (((size_t)(ra&(Bsz-1)))*Tsz + (ra>>7))*K
                               : A + (size_t)ra*K) + q0*4;
    const float* Arow1 = (perm ? A + (((size_t)(rb&(Bsz-1)))*Tsz + (rb>>7))*K
                               : A + (size_t)rb*K) + q0*4;
    const float* Wrow0 = W + (size_t)(n0+r0   )*K + q0*4;
    const float* Wrow1 = W + (size_t)(n0+r0+64)*K + q0*4;

    float C[2][8][4] = {};

    {   // prologue: tile 0 -> buffer 0
        float4 a0=*(const float4*)Arow0, a1=*(const float4*)Arow1;
        float4 b0=*(const float4*)Wrow0, b1=*(const float4*)Wrow1;
        float* p;
        p=&As[0][r0   ][q0*4]; p[0]=tf32f(a0.x);p[1]=tf32f(a0.y);p[2]=tf32f(a0.z);p[3]=tf32f(a0.w);
        p=&As[0][r0+64][q0*4]; p[0]=tf32f(a1.x);p[1]=tf32f(a1.y);p[2]=tf32f(a1.z);p[3]=tf32f(a1.w);
        p=&Bs[0][r0   ][q0*4]; p[0]=tf32f(b0.x);p[1]=tf32f(b0.y);p[2]=tf32f(b0.z);p[3]=tf32f(b0.w);
        p=&Bs[0][r0+64][q0*4]; p[0]=tf32f(b1.x);p[1]=tf32f(b1.y);p[2]=tf32f(b1.z);p[3]=tf32f(b1.w);
    }
    __syncthreads();

    const int nkb = K>>4;
    float4 na0,na1,nb0,nb1;
    for (int kb=0; kb<nkb; ++kb){
        if (kb+1<nkb){
            int k0=(kb+1)<<4;
            na0=*(const float4*)(Arow0+k0); na1=*(const float4*)(Arow1+k0);
            nb0=*(const float4*)(Wrow0+k0); nb1=*(const float4*)(Wrow1+k0);
        }
        const int cur = kb&1;
        #pragma unroll
        for (int ks=0; ks<2; ++ks){
            const int kk = ks*8;
            unsigned a[2][4];
            #pragma unroll
            for (int mt=0; mt<2; ++mt){
                int row = wm*32+mt*16;
                a[mt][0]=__float_as_uint(As[cur][row+g  ][kk+tg  ]);
                a[mt][1]=__float_as_uint(As[cur][row+g+8][kk+tg  ]);
                a[mt][2]=__float_as_uint(As[cur][row+g  ][kk+tg+4]);
                a[mt][3]=__float_as_uint(As[cur][row+g+8][kk+tg+4]);
            }
            #pragma unroll
            for (int nt=0; nt<8; ++nt){
                int col = wn*64+nt*8+g;
                unsigned b0=__float_as_uint(Bs[cur][col][kk+tg  ]);
                unsigned b1=__float_as_uint(Bs[cur][col][kk+tg+4]);
                mma8(C[0][nt], a[0], b0, b1);
                mma8(C[1][nt], a[1], b0, b1);
            }
        }
        if (kb+1<nkb){
            const int nb=(kb+1)&1;
            float* p;
            p=&As[nb][r0   ][q0*4]; p[0]=tf32f(na0.x);p[1]=tf32f(na0.y);p[2]=tf32f(na0.z);p[3]=tf32f(na0.w);
            p=&As[nb][r0+64][q0*4]; p[0]=tf32f(na1.x);p[1]=tf32f(na1.y);p[2]=tf32f(na1.z);p[3]=tf32f(na1.w);
            p=&Bs[nb][r0   ][q0*4]; p[0]=tf32f(nb0.x);p[1]=tf32f(nb0.y);p[2]=tf32f(nb0.z);p[3]=tf32f(nb0.w);
            p=&Bs[nb][r0+64][q0*4]; p[0]=tf32f(nb1.x);p[1]=tf32f(nb1.y);p[2]=tf32f(nb1.z);p[3]=tf32f(nb1.w);
            __syncthreads();
        }
    }

    #pragma unroll
    for (int mt=0; mt<2; ++mt){
        #pragma unroll
        for (int nt=0; nt<8; ++nt){
            int row = m0 + wm*32 + mt*16 + g;
            int col = n0 + wn*64 + nt*8 + 2*tg;
            float bb0 = bias[col], bb1 = bias[col+1];
            float2 v;
            v.x = C[mt][nt][0]+bb0; v.y = C[mt][nt][1]+bb1;
            *(float2*)&g_xi[(size_t)row*G3sz+col] = v;
            v.x = C[mt][nt][2]+bb0; v.y = C[mt][nt][3]+bb1;
            *(float2*)&g_xi[(size_t)(row+8)*G3sz+col] = v;
        }
    }
}

// ---------------- 2) persistent GRU scan v7: 32 warps, split-K 4, r7 barrier ----------------
__device__ __forceinline__ void stage2(const float* __restrict__ hb, int m0, int kg0,
                                       float* buf, int lane){
    #pragma unroll
    for (int j=0;j<2;++j){
        int idx = lane + j*32;          // 0..63 : 16 rows x 4 segs(16B)
        int row = idx>>2, c4 = idx&3;
        const float* src = hb + (size_t)(m0+row)*Hsz + kg0 + c4*4;
        unsigned dst = (unsigned)__cvta_generic_to_shared(buf + row*HST2 + c4*4);
        asm volatile("cp.async.cg.shared.global [%0], [%1], 16;" :: "r"(dst), "l"(src));
    }
    asm volatile("cp.async.commit_group;" ::: "memory");
}

__global__ void __launch_bounds__(1024) k_scan(const float* __restrict__ whh,
        const float* __restrict__ bhh, int sel)
{
    extern __shared__ float sm[];
    float2* Wp = (float2*)sm;              // [GR][WST2] fragment-paired tf32 w_hh
    float*  bh = sm + OFF_BH;              // [GR] biases
    float*  Gs = sm + OFF_GS;              // [2][128][GS] split-K partial gates
    float*  Hb = sm + OFF_HB;              // [32][2][WBUF] per-warp staging rings

    float* hs = (sel==1) ? g_hsA : g_hsB;
    const float* xi = g_xi;

    const int tid = threadIdx.x, bx = blockIdx.x;
    const int lane = tid&31, wid = tid>>5;
    const int g = lane>>2, tg = lane&3;
    const int kh = wid&3, mg = wid>>2;     // K-quarter, m-group (8 x 16 rows)
    const int m0 = mg*16;
    const int kbase = kh*256;
    float* mybuf = Hb + wid*(2*WBUF);
    float* Gmy   = Gs + (kh>>1)*(Bsz*GS);  // buffer 0: kh 0,1; buffer 1: kh 2,3

    // prologue: fragment-paired tf32 weights (pair = k elems {kk+tg, kk+tg+4})
    for (int idx = tid; idx < GR*512; idx += 1024){
        int r = idx>>9, p = idx&511;
        int k0 = (p>>2)<<3, tp = p&3;
        int gt = r>>3, u = r&7;
        const float* w = whh + ((size_t)(gt*Hsz + bx*UPC + u))*Hsz;
        Wp[r*WST2 + (p>>2)*4 + tp] = make_float2(tf32f(w[k0+tp]), tf32f(w[k0+tp+4]));
    }
    if (tid < GR){ int gt=tid>>3, u=tid&7; bh[tid] = bhh[gt*Hsz + bx*UPC + u]; }
    __syncthreads();

    const int eu = tid&7, eb = tid>>3;     // epilogue: unit, batch row (1 pair/thread)
    const int ucol = bx*UPC + eu;
    const float br = bh[eu], bz = bh[UPC+eu], bn = bh[2*UPC+eu];
    float hprev = 0.f;                     // register-carried own h_old

    for (int t=0; t<Tsz; ++t){
        const float* hb = hs + (size_t)(t-1)*BH;   // deref'd only when t>0

        // prefetch epilogue xi inputs (latency hides under mma phase)
        const float* xb = xi + ((size_t)t*Bsz + eb)*G3sz + bx*UPC + eu;
        float pxr = xb[0], pxz = xb[Hsz], pxn = xb[2*Hsz];

        float C[3][4] = {};
        if (t>0){
            stage2(hb, m0, kbase, mybuf, lane);
            for (int c=0; c<NCH; ++c){
                if (c+1 < NCH){
                    stage2(hb, m0, kbase + (c+1)*CH, mybuf + ((c+1)&1)*WBUF, lane);
                    asm volatile("cp.async.wait_group 1;" ::: "memory");
                } else {
                    asm volatile("cp.async.wait_group 0;" ::: "memory");
                }
                __syncwarp();
                const float* war = mybuf + (c&1)*WBUF + g*HST2 + tg;
                const int kp0 = ((kbase + c*CH)>>3)*4 + tg;
                #pragma unroll
                for (int kk=0; kk<CH; kk+=8){
                    unsigned a[4];
                    a[0]=tf32u(war[kk]);      a[1]=tf32u(war[8*HST2+kk]);
                    a[2]=tf32u(war[kk+4]);    a[3]=tf32u(war[8*HST2+kk+4]);
                    const int kp = kp0 + (kk>>3)*4;
                    #pragma unroll
                    for (int nt=0; nt<3; ++nt){
                        float2 bp = Wp[(nt*8+g)*WST2 + kp];
                        mma8(C[nt], a, __float_as_uint(bp.x), __float_as_uint(bp.y));
                    }
                }
            }
            if ((kh&1)==0){    // kh 0,2 write their buffer
                #pragma unroll
                for (int nt=0; nt<3; ++nt){
                    int row = m0+g, col = nt*8+2*tg;
                    *(float2*)&Gmy[row*GS+col]     = make_float2(C[nt][0], C[nt][1]);
                    *(float2*)&Gmy[(row+8)*GS+col] = make_float2(C[nt][2], C[nt][3]);
                }
            }
        }
        __syncthreads();
        if (t>0 && (kh&1)==1){   // kh 1,3 accumulate into the same buffer
            #pragma unroll
            for (int nt=0; nt<3; ++nt){
                int row = m0+g, col = nt*8+2*tg;
                float2 v0 = *(float2*)&Gmy[row*GS+col];
                float2 v1 = *(float2*)&Gmy[(row+8)*GS+col];
                v0.x += C[nt][0]; v0.y += C[nt][1];
                v1.x += C[nt][2]; v1.y += C[nt][3];
                *(float2*)&Gmy[row*GS+col]     = v0;
                *(float2*)&Gmy[(row+8)*GS+col] = v1;
            }
        }
        __syncthreads();

        // epilogue: 1 (b,u) pair per thread; sum the two split-K buffers
        {
            float Gr=0.f, Gz=0.f, Gn=0.f;
            if (t>0){
                Gr = Gs[eb*GS+eu]       + Gs[Bsz*GS + eb*GS+eu];
                Gz = Gs[eb*GS+UPC+eu]   + Gs[Bsz*GS + eb*GS+UPC+eu];
                Gn = Gs[eb*GS+2*UPC+eu] + Gs[Bsz*GS + eb*GS+2*UPC+eu];
            }
            float r  = fast_sigmoid(pxr + Gr + br);
            float z  = fast_sigmoid(pxz + Gz + bz);
            float nn = fast_tanh(pxn + r*(Gn + bn));
            float hn = (1.f - z)*nn + z*hprev;
            hprev = hn;
            hs[((size_t)t*Bsz + eb)*Hsz + ucol] = hn;
        }

        if (t < Tsz-1){
            __threadfence();
            grid_barrier();
        }
    }
}

// ---------------- 3) FC: out[b][p] = h_last[b] . fc_w[p] + fc_b[p] ----------------
__global__ void k_fc(const float* __restrict__ fw, const float* __restrict__ fb,
                     float* __restrict__ out)
{
    __shared__ float w[Hsz];
    const int p = blockIdx.x, b = threadIdx.x;
    for (int k=b; k<Hsz; k+=Bsz) w[k] = fw[(size_t)p*Hsz + k];
    __syncthreads();
    const float* h = g_hsA + ((size_t)(Tsz-1)*Bsz + b)*Hsz;
    float s = 0.f;
    #pragma unroll 8
    for (int k=0; k<Hsz; ++k) s += h[k]*w[k];
    out[b*PREDsz + p] = s + fb[p];
}

// ---------------- launch ----------------
extern "C" void kernel_launch(void* const* d_in, const int* in_sizes, int n_in,
                              void* d_out, int out_size)
{
    const float* x    = (const float*)d_in[0];
    const float* wih0 = (const float*)d_in[1];
    const float* whh0 = (const float*)d_in[2];
    const float* bih0 = (const float*)d_in[3];
    const float* bhh0 = (const float*)d_in[4];
    const float* wih1 = (const float*)d_in[5];
    const float* whh1 = (const float*)d_in[6];
    const float* bih1 = (const float*)d_in[7];
    const float* bhh1 = (const float*)d_in[8];
    const float* wih2 = (const float*)d_in[9];
    const float* whh2 = (const float*)d_in[10];
    const float* bih2 = (const float*)d_in[11];
    const float* bhh2 = (const float*)d_in[12];
    const float* fcw  = (const float*)d_in[13];
    const float* fcb  = (const float*)d_in[14];
    float* out = (float*)d_out;

    cudaFuncSetAttribute(k_scan, cudaFuncAttributeMaxDynamicSharedMemorySize, SCAN_SMEM_BYTES);

    dim3 gg(G3sz/128, MR/128);   // n fastest for L2 reuse

    // layer 0 (input x, permuted [B,T,IN] -> row t*B+b)
    k_gemm<<<gg, 256>>>(x, 0, wih0, bih0, INsz, 1);
    k_scan<<<NCTA, 1024, SCAN_SMEM_BYTES>>>(whh0, bhh0, 1);
    // layer 1
    k_gemm<<<gg, 256>>>(nullptr, 1, wih1, bih1, Hsz, 0);
    k_scan<<<NCTA, 1024, SCAN_SMEM_BYTES>>>(whh1, bhh1, 2);
    // layer 2
    k_gemm<<<gg, 256>>>(nullptr, 2, wih2, bih2, Hsz, 0);
    k_scan<<<NCTA, 1024, SCAN_SMEM_BYTES>>>(whh2, bhh2, 1);
    // head
    k_fc<<<PREDsz, Bsz>>>(fcw, fcb, out);
}

// round 12
// speedup vs baseline: 1.6272x; 1.0765x over previous
#include <cuda_runtime.h>
#include <cuda_bf16.h>
#include <cstdint>

// Problem dims
#define Bsz   128
#define Tsz   512
#define INsz  128
#define Hsz   1024
#define G3sz  3072
#define PREDsz 96
#define MR    (Tsz*Bsz)        // 65536 rows
#define BH    (Bsz*Hsz)        // 131072

// Scan kernel config: 128 persistent CTAs, 8 hidden units each, 16 warps (split-K 2)
#define NCTA  128
#define UPC   8                // units per CTA
#define GR    (3*UPC)          // gate rows per CTA = 24
#define WST2  516              // Wp row stride in float2 (conflict-free LDS.64)
#define GS    26               // Gs row stride (floats)
#define CH    32               // staging chunk columns
#define NCH   16               // chunks per K-half (512/32)
#define HST2  40               // staging row stride: (8g+2tg) distinct per 16-lane phase -> LDS.64 conflict-free
#define WBUF  (16*HST2)        // 640 floats: one 16-row staging buffer
// SMEM map (floats): Wp | bias | Gs[2] | Hb[16 warps][2 bufs]
#define OFF_BH   (GR*WST2*2)                  // 24768
#define OFF_GS   (OFF_BH + 32)                // 24800
#define OFF_HB   (OFF_GS + 2*Bsz*GS)          // 31456
#define SCAN_SMEM_FLOATS (OFF_HB + 16*2*WBUF) // 51936
#define SCAN_SMEM_BYTES  (SCAN_SMEM_FLOATS*4) // 207744 B

// ---------------- device scratch (allocation-free rule) ----------------
// h buffers hold PAIR-PERMUTED tf32-rounded h: within each aligned group of 8
// columns, logical col w is stored at position (w&3)*2 + (w>>2).
__device__ float g_xi [(size_t)MR*G3sz];   // [T,B,3H] input-side gate projections
__device__ float g_hsA[(size_t)MR*Hsz];    // [T,B,H] hidden sequence (permuted tf32)
__device__ float g_hsB[(size_t)MR*Hsz];    // [T,B,H] hidden sequence (permuted tf32)
__device__ unsigned g_bar_cnt = 0;
__device__ unsigned g_bar_gen = 0;

// ---------------- helpers ----------------
__device__ __forceinline__ unsigned tf32u(float f){
    unsigned u; asm("cvt.rna.tf32.f32 %0, %1;" : "=r"(u) : "f"(f));
    return u;
}
__device__ __forceinline__ float tf32f(float f){ return __uint_as_float(tf32u(f)); }

__device__ __forceinline__ void mma8(float* d, const unsigned* a, unsigned b0, unsigned b1){
    asm volatile("mma.sync.aligned.m16n8k8.row.col.f32.tf32.tf32.f32 "
        "{%0,%1,%2,%3},{%4,%5,%6,%7},{%8,%9},{%0,%1,%2,%3};"
        : "+f"(d[0]),"+f"(d[1]),"+f"(d[2]),"+f"(d[3])
        : "r"(a[0]),"r"(a[1]),"r"(a[2]),"r"(a[3]),"r"(b0),"r"(b1));
}

__device__ __forceinline__ float fast_sigmoid(float x){
    return 1.f/(1.f + __expf(-x));
}
__device__ __forceinline__ float fast_tanh(float x){
    float ax = fabsf(x);
    float e  = __expf(2.f*ax);
    float th = 1.f - 2.f/(e + 1.f);
    return copysignf(th, x);
}

// software grid barrier (round-7 proven single-address ticket barrier)
__device__ __forceinline__ void grid_barrier(){
    __syncthreads();
    if (threadIdx.x == 0){
        unsigned gen = atomicAdd(&g_bar_gen, 0u);
        unsigned t   = atomicAdd(&g_bar_cnt, 1u);
        if (t == NCTA-1){
            atomicExch(&g_bar_cnt, 0u);
            __threadfence();
            atomicAdd(&g_bar_gen, 1u);
        } else {
            while (atomicAdd(&g_bar_gen, 0u) == gen) { __nanosleep(32); }
        }
        __threadfence();
    }
    __syncthreads();
}

// Store a float4 row-segment of A into SMEM, un-permuting if the source is a
// pair-permuted h buffer. Stored position p within a group of 8 holds logical
// column (p>>1) + (p&1)*4, so the 4 loaded values (positions q0*4..q0*4+3) go
// to logical cols base8 + {0,4,1,5} + (q0&1)*2.
__device__ __forceinline__ void storeA(float* rowbase, int q0, float4 v, int permA){
    if (!permA){
        float* p = rowbase + q0*4;
        p[0]=tf32f(v.x); p[1]=tf32f(v.y); p[2]=tf32f(v.z); p[3]=tf32f(v.w);
    } else {
        int b8 = (q0>>1)*8 + (q0&1)*2;
        rowbase[b8+0] = v.x;   // already tf32-rounded at producer
        rowbase[b8+4] = v.y;
        rowbase[b8+1] = v.z;
        rowbase[b8+5] = v.w;
    }
}

// ---------------- 1) XI = A @ W^T + bias  (tf32 mma, 128x128 tiles) ----------------
__global__ void __launch_bounds__(256) k_gemm(const float* __restrict__ ext, int sel,
        const float* __restrict__ W, const float* __restrict__ bias,
        int K, int rowperm, int permA)
{
    __shared__ float As[2][128][20];
    __shared__ float Bs[2][128][20];

    const float* A = ext ? ext : (sel==1 ? g_hsA : g_hsB);

    const int tid = threadIdx.x;
    const int lane = tid&31, wid = tid>>5;
    const int g = lane>>2, tg = lane&3;
    const int wm = wid&3, wn = wid>>2;           // 4 x 2 warps, warp tile 32x64
    const int n0 = blockIdx.x*128, m0 = blockIdx.y*128;
    const int r0 = tid>>2, q0 = tid&3;

    int ra = m0 + r0, rb = m0 + r0 + 64;
    const float* Arow0 = (rowperm ? A + (((size_t)(ra&(Bsz-1)))*Tsz + (ra>>7))*K
                                  : A + (size_t)ra*K) + q0*4;
    const float* Arow1 = (rowperm ? A + (((size_t)(rb&(Bsz-1)))*Tsz + (rb>>7))*K
                                  : A + (size_t)rb*K) + q0*4;
    const float* Wrow0 = W + (size_t)(n0+r0   )*K + q0*4;
    const float* Wrow1 = W + (size_t)(n0+r0+64)*K + q0*4;

    float C[2][8][4] = {};

    {   // prologue: tile 0 -> buffer 0
        float4 a0=*(const float4*)Arow0, a1=*(const float4*)Arow1;
        float4 b0=*(const float4*)Wrow0, b1=*(const float4*)Wrow1;
        storeA(&As[0][r0   ][0], q0, a0, permA);
        storeA(&As[0][r0+64][0], q0, a1, permA);
        float* p;
        p=&Bs[0][r0   ][q0*4]; p[0]=tf32f(b0.x);p[1]=tf32f(b0.y);p[2]=tf32f(b0.z);p[3]=tf32f(b0.w);
        p=&Bs[0][r0+64][q0*4]; p[0]=tf32f(b1.x);p[1]=tf32f(b1.y);p[2]=tf32f(b1.z);p[3]=tf32f(b1.w);
    }
    __syncthreads();

    const int nkb = K>>4;
    float4 na0,na1,nb0,nb1;
    for (int kb=0; kb<nkb; ++kb){
        if (kb+1<nkb){
            int k0=(kb+1)<<4;
            na0=*(const float4*)(Arow0+k0); na1=*(const float4*)(Arow1+k0);
            nb0=*(const float4*)(Wrow0+k0); nb1=*(const float4*)(Wrow1+k0);
        }
        const int cur = kb&1;
        #pragma unroll
        for (int ks=0; ks<2; ++ks){
            const int kk = ks*8;
            unsigned a[2][4];
            #pragma unroll
            for (int mt=0; mt<2; ++mt){
                int row = wm*32+mt*16;
                a[mt][0]=__float_as_uint(As[cur][row+g  ][kk+tg  ]);
                a[mt][1]=__float_as_uint(As[cur][row+g+8][kk+tg  ]);
                a[mt][2]=__float_as_uint(As[cur][row+g  ][kk+tg+4]);
                a[mt][3]=__float_as_uint(As[cur][row+g+8][kk+tg+4]);
            }
            #pragma unroll
            for (int nt=0; nt<8; ++nt){
                int col = wn*64+nt*8+g;
                unsigned b0=__float_as_uint(Bs[cur][col][kk+tg  ]);
                unsigned b1=__float_as_uint(Bs[cur][col][kk+tg+4]);
                mma8(C[0][nt], a[0], b0, b1);
                mma8(C[1][nt], a[1], b0, b1);
            }
        }
        if (kb+1<nkb){
            const int nb=(kb+1)&1;
            storeA(&As[nb][r0   ][0], q0, na0, permA);
            storeA(&As[nb][r0+64][0], q0, na1, permA);
            float* p;
            p=&Bs[nb][r0   ][q0*4]; p[0]=tf32f(nb0.x);p[1]=tf32f(nb0.y);p[2]=tf32f(nb0.z);p[3]=tf32f(nb0.w);
            p=&Bs[nb][r0+64][q0*4]; p[0]=tf32f(nb1.x);p[1]=tf32f(nb1.y);p[2]=tf32f(nb1.z);p[3]=tf32f(nb1.w);
            __syncthreads();
        }
    }

    #pragma unroll
    for (int mt=0; mt<2; ++mt){
        #pragma unroll
        for (int nt=0; nt<8; ++nt){
            int row = m0 + wm*32 + mt*16 + g;
            int col = n0 + wn*64 + nt*8 + 2*tg;
            float bb0 = bias[col], bb1 = bias[col+1];
            float2 v;
            v.x = C[mt][nt][0]+bb0; v.y = C[mt][nt][1]+bb1;
            *(float2*)&g_xi[(size_t)row*G3sz+col] = v;
            v.x = C[mt][nt][2]+bb0; v.y = C[mt][nt][3]+bb1;
            *(float2*)&g_xi[(size_t)(row+8)*G3sz+col] = v;
        }
    }
}

// ---------------- 2) persistent GRU scan v8: r7 skeleton, permuted-tf32 h ----------------
__device__ __forceinline__ void stage2(const float* __restrict__ hb, int m0, int kg0,
                                       float* buf, int lane){
    #pragma unroll
    for (int j=0;j<4;++j){
        int idx = lane + j*32;          // 0..127 : 16 rows x 8 segs(16B)
        int row = idx>>3, c4 = idx&7;
        const float* src = hb + (size_t)(m0+row)*Hsz + kg0 + c4*4;
        unsigned dst = (unsigned)__cvta_generic_to_shared(buf + row*HST2 + c4*4);
        asm volatile("cp.async.cg.shared.global [%0], [%1], 16;" :: "r"(dst), "l"(src));
    }
    asm volatile("cp.async.commit_group;" ::: "memory");
}

__global__ void __launch_bounds__(512) k_scan(const float* __restrict__ whh,
        const float* __restrict__ bhh, int sel)
{
    extern __shared__ float sm[];
    float2* Wp = (float2*)sm;              // [GR][WST2] fragment-paired tf32 w_hh
    float*  bh = sm + OFF_BH;              // [GR] biases
    float*  Gs = sm + OFF_GS;              // [2][128][GS] split-K partial gates
    float*  Hb = sm + OFF_HB;              // [16][2][WBUF] per-warp staging rings

    float* hs = (sel==1) ? g_hsA : g_hsB;
    const float* xi = g_xi;

    const int tid = threadIdx.x, bx = blockIdx.x;
    const int lane = tid&31, wid = tid>>5;
    const int g = lane>>2, tg = lane&3;
    const int kh = wid&1, mg = wid>>1;     // K-half, m-group
    const int m0 = mg*16;
    const int kbase = kh*512;
    float* mybuf = Hb + wid*(2*WBUF);
    float* Gmy   = Gs + kh*(Bsz*GS);

    // prologue: fragment-paired tf32 weights (pair = k elems {kk+tg, kk+tg+4})
    for (int idx = tid; idx < GR*512; idx += 512){
        int r = idx>>9, p = idx&511;
        int k0 = (p>>2)<<3, tp = p&3;
        int gt = r>>3, u = r&7;
        const float* w = whh + ((size_t)(gt*Hsz + bx*UPC + u))*Hsz;
        Wp[r*WST2 + (p>>2)*4 + tp] = make_float2(tf32f(w[k0+tp]), tf32f(w[k0+tp+4]));
    }
    if (tid < GR){ int gt=tid>>3, u=tid&7; bh[tid] = bhh[gt*Hsz + bx*UPC + u]; }
    __syncthreads();

    const int eu = tid&7, eb0 = (tid>>3)*2;   // epilogue: unit, 2 batch rows
    const int pcol = bx*UPC + (eu&3)*2 + (eu>>2);  // pair-permuted store column
    const float br = bh[eu], bz = bh[UPC+eu], bn = bh[2*UPC+eu];
    float hprev[2] = {0.f, 0.f};              // register-carried own h_old (fp32)

    for (int t=0; t<Tsz; ++t){
        const float* hb = hs + (size_t)(t-1)*BH;   // deref'd only when t>0

        // prefetch epilogue xi inputs (latency hides under mma phase)
        float pxr[2], pxz[2], pxn[2];
        #pragma unroll
        for (int i=0;i<2;++i){
            int b = eb0 + i;
            const float* xb = xi + ((size_t)t*Bsz + b)*G3sz + bx*UPC + eu;
            pxr[i]=xb[0]; pxz[i]=xb[Hsz]; pxn[i]=xb[2*Hsz];
        }

        if (t>0){
            float C[3][4] = {};
            stage2(hb, m0, kbase, mybuf, lane);
            for (int c=0; c<NCH; ++c){
                if (c+1 < NCH){
                    stage2(hb, m0, kbase + (c+1)*CH, mybuf + ((c+1)&1)*WBUF, lane);
                    asm volatile("cp.async.wait_group 1;" ::: "memory");
                } else {
                    asm volatile("cp.async.wait_group 0;" ::: "memory");
                }
                __syncwarp();
                const float* war  = mybuf + (c&1)*WBUF + g*HST2;
                const float* war8 = war + 8*HST2;
                const int kp0 = ((kbase + c*CH)>>3)*4 + tg;
                #pragma unroll
                for (int gi=0; gi<4; ++gi){
                    float2 fa0 = *(const float2*)(war  + gi*8 + tg*2);  // (a0, a2)
                    float2 fa1 = *(const float2*)(war8 + gi*8 + tg*2);  // (a1, a3)
                    unsigned a[4];
                    a[0]=__float_as_uint(fa0.x); a[1]=__float_as_uint(fa1.x);
                    a[2]=__float_as_uint(fa0.y); a[3]=__float_as_uint(fa1.y);
                    const int kp = kp0 + gi*4;
                    #pragma unroll
                    for (int nt=0; nt<3; ++nt){
                        float2 bp = Wp[(nt*8+g)*WST2 + kp];
                        mma8(C[nt], a, __float_as_uint(bp.x), __float_as_uint(bp.y));
                    }
                }
            }
            #pragma unroll
            for (int nt=0; nt<3; ++nt){
                int row = m0+g, col = nt*8+2*tg;
                *(float2*)&Gmy[row*GS+col]     = make_float2(C[nt][0], C[nt][1]);
                *(float2*)&Gmy[(row+8)*GS+col] = make_float2(C[nt][2], C[nt][3]);
            }
        }
        __syncthreads();

        // epilogue: 2 (b,u) pairs per thread; sum the two split-K partials
        #pragma unroll
        for (int i=0; i<2; ++i){
            int b = eb0 + i;
            float Gr=0.f, Gz=0.f, Gn=0.f;
            if (t>0){
                Gr = Gs[b*GS+eu]       + Gs[Bsz*GS + b*GS+eu];
                Gz = Gs[b*GS+UPC+eu]   + Gs[Bsz*GS + b*GS+UPC+eu];
                Gn = Gs[b*GS+2*UPC+eu] + Gs[Bsz*GS + b*GS+2*UPC+eu];
            }
            float r  = fast_sigmoid(pxr[i] + Gr + br);
            float z  = fast_sigmoid(pxz[i] + Gz + bz);
            float nn = fast_tanh(pxn[i] + r*(Gn + bn));
            float hn = (1.f - z)*nn + z*hprev[i];
            hprev[i] = hn;
            hs[((size_t)t*Bsz + b)*Hsz + pcol] = tf32f(hn);
        }

        if (t < Tsz-1){
            __threadfence();
            grid_barrier();
        }
    }
}

// ---------------- 3) FC: out[b][p] = h_last[b] . fc_w[p] + fc_b[p] ----------------
// h is stored pair-permuted: stored position p in a group of 8 holds logical
// column (p>>1) + (p&1)*4.
__global__ void k_fc(const float* __restrict__ fw, const float* __restrict__ fb,
                     float* __restrict__ out)
{
    __shared__ float w[Hsz];
    const int p = blockIdx.x, b = threadIdx.x;
    for (int k=b; k<Hsz; k+=Bsz) w[k] = fw[(size_t)p*Hsz + k];
    __syncthreads();
    const float* h = g_hsA + ((size_t)(Tsz-1)*Bsz + b)*Hsz;
    float s = 0.f;
    #pragma unroll 8
    for (int k=0; k<Hsz; ++k){
        int sp = k&7;
        int logical = (k & ~7) + (sp>>1) + (sp&1)*4;
        s += h[k]*w[logical];
    }
    out[b*PREDsz + p] = s + fb[p];
}

// ---------------- launch ----------------
extern "C" void kernel_launch(void* const* d_in, const int* in_sizes, int n_in,
                              void* d_out, int out_size)
{
    const float* x    = (const float*)d_in[0];
    const float* wih0 = (const float*)d_in[1];
    const float* whh0 = (const float*)d_in[2];
    const float* bih0 = (const float*)d_in[3];
    const float* bhh0 = (const float*)d_in[4];
    const float* wih1 = (const float*)d_in[5];
    const float* whh1 = (const float*)d_in[6];
    const float* bih1 = (const float*)d_in[7];
    const float* bhh1 = (const float*)d_in[8];
    const float* wih2 = (const float*)d_in[9];
    const float* whh2 = (const float*)d_in[10];
    const float* bih2 = (const float*)d_in[11];
    const float* bhh2 = (const float*)d_in[12];
    const float* fcw  = (const float*)d_in[13];
    const float* fcb  = (const float*)d_in[14];
    float* out = (float*)d_out;

    cudaFuncSetAttribute(k_scan, cudaFuncAttributeMaxDynamicSharedMemorySize, SCAN_SMEM_BYTES);

    dim3 gg(G3sz/128, MR/128);   // n fastest for L2 reuse

    // layer 0 (input x, row-permuted [B,T,IN] view, columns unpermuted)
    k_gemm<<<gg, 256>>>(x, 0, wih0, bih0, INsz, 1, 0);
    k_scan<<<NCTA, 512, SCAN_SMEM_BYTES>>>(whh0, bhh0, 1);
    // layer 1 (A = permuted-tf32 h from layer 0)
    k_gemm<<<gg, 256>>>(nullptr, 1, wih1, bih1, Hsz, 0, 1);
    k_scan<<<NCTA, 512, SCAN_SMEM_BYTES>>>(whh1, bhh1, 2);
    // layer 2
    k_gemm<<<gg, 256>>>(nullptr, 2, wih2, bih2, Hsz, 0, 1);
    k_scan<<<NCTA, 512, SCAN_SMEM_BYTES>>>(whh2, bhh2, 1);
    // head
    k_fc<<<PREDsz, Bsz>>>(fcw, fcb, out);
}

// round 13
// speedup vs baseline: 1.6580x; 1.0189x over previous
#include <cuda_runtime.h>
#include <cuda_bf16.h>
#include <cstdint>

// Problem dims
#define Bsz   128
#define Tsz   512
#define INsz  128
#define Hsz   1024
#define G3sz  3072
#define PREDsz 96
#define MR    (Tsz*Bsz)        // 65536 rows
#define BH    (Bsz*Hsz)        // 131072

// Scan kernel config (round-7 champion): 128 CTAs, 8 units each, 16 warps (split-K 2)
#define NCTA  128
#define UPC   8                // units per CTA
#define GR    (3*UPC)          // gate rows per CTA = 24
#define WST2  516              // Wp row stride in float2 (conflict-free LDS.64)
#define GS    26               // Gs row stride (floats)
#define CH    32               // staging chunk columns
#define NCH   16               // chunks per K-half (512/32)
#define HST2  36               // staging row stride (floats)
#define WBUF  (16*HST2)        // 576 floats: one 16-row staging buffer
#define OFF_BH   (GR*WST2*2)                  // 24768
#define OFF_GS   (OFF_BH + 32)                // 24800
#define OFF_HB   (OFF_GS + 2*Bsz*GS)          // 31456
#define SCAN_SMEM_FLOATS (OFF_HB + 16*2*WBUF) // 49888
#define SCAN_SMEM_BYTES  (SCAN_SMEM_FLOATS*4) // 199552 B

// GEMM smem: As[2][128][24] + Bs[2][128][24] floats, pair-permuted k-groups
#define GST   24
#define GEMM_TILE_FLOATS (2*128*GST)
#define GEMM_SMEM_BYTES  (2*GEMM_TILE_FLOATS*4)   // 49152 B

// ---------------- device scratch (allocation-free rule) ----------------
__device__ float g_xi [(size_t)MR*G3sz];   // [T,B,3H] input-side gate projections
__device__ float g_hsA[(size_t)MR*Hsz];    // [T,B,H] hidden sequence buffer A
__device__ float g_hsB[(size_t)MR*Hsz];    // [T,B,H] hidden sequence buffer B
__device__ unsigned g_bar_cnt = 0;
__device__ unsigned g_bar_gen = 0;

// ---------------- helpers ----------------
__device__ __forceinline__ unsigned tf32u(float f){
    unsigned u; asm("cvt.rna.tf32.f32 %0, %1;" : "=r"(u) : "f"(f));
    return u;
}
__device__ __forceinline__ float tf32f(float f){ return __uint_as_float(tf32u(f)); }

__device__ __forceinline__ void mma8(float* d, const unsigned* a, unsigned b0, unsigned b1){
    asm volatile("mma.sync.aligned.m16n8k8.row.col.f32.tf32.tf32.f32 "
        "{%0,%1,%2,%3},{%4,%5,%6,%7},{%8,%9},{%0,%1,%2,%3};"
        : "+f"(d[0]),"+f"(d[1]),"+f"(d[2]),"+f"(d[3])
        : "r"(a[0]),"r"(a[1]),"r"(a[2]),"r"(a[3]),"r"(b0),"r"(b1));
}

__device__ __forceinline__ float fast_sigmoid(float x){
    return 1.f/(1.f + __expf(-x));
}
__device__ __forceinline__ float fast_tanh(float x){
    float ax = fabsf(x);
    float e  = __expf(2.f*ax);
    float th = 1.f - 2.f/(e + 1.f);
    return copysignf(th, x);
}

// software grid barrier (round-7 proven single-address ticket barrier)
__device__ __forceinline__ void grid_barrier(){
    __syncthreads();
    if (threadIdx.x == 0){
        unsigned gen = atomicAdd(&g_bar_gen, 0u);
        unsigned t   = atomicAdd(&g_bar_cnt, 1u);
        if (t == NCTA-1){
            atomicExch(&g_bar_cnt, 0u);
            __threadfence();
            atomicAdd(&g_bar_gen, 1u);
        } else {
            while (atomicAdd(&g_bar_gen, 0u) == gen) { __nanosleep(32); }
        }
        __threadfence();
    }
    __syncthreads();
}

// ---------------- 1) XI = A @ W^T + bias  (tf32 mma, 128x128 tiles) ----------------
// SMEM tiles hold pair-permuted k-groups: within each 8-wide k-group, smem
// position 2p..2p+1 holds logical k {p, p+4}. Thread q0 loads logical k
// {g0, g0+1, g0+4, g0+5} (g0 = (q0>>1)*8 + (q0&1)*2) as 2x LDG.64 and stores
// one contiguous STS.128 at smem col q0*4. Fragment fetch = LDS.64 pairs.
__global__ void __launch_bounds__(256) k_gemm(const float* __restrict__ ext, int sel,
        const float* __restrict__ W, const float* __restrict__ bias,
        int K, int perm)
{
    extern __shared__ float dsm[];
    float (*As)[128][GST] = (float(*)[128][GST])dsm;
    float (*Bs)[128][GST] = (float(*)[128][GST])(dsm + GEMM_TILE_FLOATS);

    const float* A = ext ? ext : (sel==1 ? g_hsA : g_hsB);

    const int tid = threadIdx.x;
    const int lane = tid&31, wid = tid>>5;
    const int g = lane>>2, tg = lane&3;
    const int wm = wid&3, wn = wid>>2;           // 4 x 2 warps, warp tile 32x64
    const int n0 = blockIdx.x*128, m0 = blockIdx.y*128;
    const int r0 = tid>>2, q0 = tid&3;
    const int g0 = (q0>>1)*8 + (q0&1)*2;         // logical k base for this thread

    int ra = m0 + r0, rb = m0 + r0 + 64;
    const float* Arow0 = (perm ? A + (((size_t)(ra&(Bsz-1)))*Tsz + (ra>>7))*K
                               : A + (size_t)ra*K) + g0;
    const float* Arow1 = (perm ? A + (((size_t)(rb&(Bsz-1)))*Tsz + (rb>>7))*K
                               : A + (size_t)rb*K) + g0;
    const float* Wrow0 = W + (size_t)(n0+r0   )*K + g0;
    const float* Wrow1 = W + (size_t)(n0+r0+64)*K + g0;

    float C[2][8][4] = {};

    // stage one 16-wide k-block (pair-permuted) from 2x float2 into 1x float4 store
    #define STAGE4(dst, src, off) do{                                   \
        float2 _va = *(const float2*)((src) + (off));                   \
        float2 _vb = *(const float2*)((src) + (off) + 4);               \
        float* _p = (dst);                                              \
        _p[0]=tf32f(_va.x); _p[1]=tf32f(_vb.x);                         \
        _p[2]=tf32f(_va.y); _p[3]=tf32f(_vb.y);                         \
    }while(0)

    {   // prologue: tile 0 -> buffer 0
        STAGE4(&As[0][r0   ][q0*4], Arow0, 0);
        STAGE4(&As[0][r0+64][q0*4], Arow1, 0);
        STAGE4(&Bs[0][r0   ][q0*4], Wrow0, 0);
        STAGE4(&Bs[0][r0+64][q0*4], Wrow1, 0);
    }
    __syncthreads();

    const int nkb = K>>4;
    for (int kb=0; kb<nkb; ++kb){
        float2 na0a,na0b,na1a,na1b,nb0a,nb0b,nb1a,nb1b;
        if (kb+1<nkb){
            int k0=(kb+1)<<4;
            na0a=*(const float2*)(Arow0+k0); na0b=*(const float2*)(Arow0+k0+4);
            na1a=*(const float2*)(Arow1+k0); na1b=*(const float2*)(Arow1+k0+4);
            nb0a=*(const float2*)(Wrow0+k0); nb0b=*(const float2*)(Wrow0+k0+4);
            nb1a=*(const float2*)(Wrow1+k0); nb1b=*(const float2*)(Wrow1+k0+4);
        }
        const int cur = kb&1;
        #pragma unroll
        for (int ks=0; ks<2; ++ks){
            const int kp = ks*8 + tg*2;          // paired col offset
            unsigned a[2][4];
            #pragma unroll
            for (int mt=0; mt<2; ++mt){
                int row = wm*32+mt*16;
                float2 fa0 = *(const float2*)&As[cur][row+g  ][kp];  // (a0,a2)
                float2 fa1 = *(const float2*)&As[cur][row+g+8][kp];  // (a1,a3)
                a[mt][0]=__float_as_uint(fa0.x); a[mt][1]=__float_as_uint(fa1.x);
                a[mt][2]=__float_as_uint(fa0.y); a[mt][3]=__float_as_uint(fa1.y);
            }
            #pragma unroll
            for (int nt=0; nt<8; ++nt){
                int col = wn*64+nt*8+g;
                float2 fb = *(const float2*)&Bs[cur][col][kp];        // (b0,b1)
                mma8(C[0][nt], a[0], __float_as_uint(fb.x), __float_as_uint(fb.y));
                mma8(C[1][nt], a[1], __float_as_uint(fb.x), __float_as_uint(fb.y));
            }
        }
        if (kb+1<nkb){
            const int nb=(kb+1)&1;
            float* p;
            p=&As[nb][r0   ][q0*4]; p[0]=tf32f(na0a.x);p[1]=tf32f(na0b.x);p[2]=tf32f(na0a.y);p[3]=tf32f(na0b.y);
            p=&As[nb][r0+64][q0*4]; p[0]=tf32f(na1a.x);p[1]=tf32f(na1b.x);p[2]=tf32f(na1a.y);p[3]=tf32f(na1b.y);
            p=&Bs[nb][r0   ][q0*4]; p[0]=tf32f(nb0a.x);p[1]=tf32f(nb0b.x);p[2]=tf32f(nb0a.y);p[3]=tf32f(nb0b.y);
            p=&Bs[nb][r0+64][q0*4]; p[0]=tf32f(nb1a.x);p[1]=tf32f(nb1b.x);p[2]=tf32f(nb1a.y);p[3]=tf32f(nb1b.y);
            __syncthreads();
        }
    }
    #undef STAGE4

    #pragma unroll
    for (int mt=0; mt<2; ++mt){
        #pragma unroll
        for (int nt=0; nt<8; ++nt){
            int row = m0 + wm*32 + mt*16 + g;
            int col = n0 + wn*64 + nt*8 + 2*tg;
            float bb0 = bias[col], bb1 = bias[col+1];
            float2 v;
            v.x = C[mt][nt][0]+bb0; v.y = C[mt][nt][1]+bb1;
            *(float2*)&g_xi[(size_t)row*G3sz+col] = v;
            v.x = C[mt][nt][2]+bb0; v.y = C[mt][nt][3]+bb1;
            *(float2*)&g_xi[(size_t)(row+8)*G3sz+col] = v;
        }
    }
}

// ---------------- 2) persistent GRU scan (round-7 champion + register hprev) ----------------
__device__ __forceinline__ void stage2(const float* __restrict__ hb, int m0, int kg0,
                                       float* buf, int lane){
    #pragma unroll
    for (int j=0;j<4;++j){
        int idx = lane + j*32;          // 0..127 : 16 rows x 8 segs(16B)
        int row = idx>>3, c4 = idx&7;
        const float* src = hb + (size_t)(m0+row)*Hsz + kg0 + c4*4;
        unsigned dst = (unsigned)__cvta_generic_to_shared(buf + row*HST2 + c4*4);
        asm volatile("cp.async.cg.shared.global [%0], [%1], 16;" :: "r"(dst), "l"(src));
    }
    asm volatile("cp.async.commit_group;" ::: "memory");
}

__global__ void __launch_bounds__(512) k_scan(const float* __restrict__ whh,
        const float* __restrict__ bhh, int sel)
{
    extern __shared__ float sm[];
    float2* Wp = (float2*)sm;              // [GR][WST2] fragment-paired tf32 w_hh
    float*  bh = sm + OFF_BH;              // [GR] biases
    float*  Gs = sm + OFF_GS;              // [2][128][GS] split-K partial gates
    float*  Hb = sm + OFF_HB;              // [16][2][WBUF] per-warp staging rings

    float* hs = (sel==1) ? g_hsA : g_hsB;
    const float* xi = g_xi;

    const int tid = threadIdx.x, bx = blockIdx.x;
    const int lane = tid&31, wid = tid>>5;
    const int g = lane>>2, tg = lane&3;
    const int kh = wid&1, mg = wid>>1;     // K-half, m-group
    const int m0 = mg*16;
    const int kbase = kh*512;
    float* mybuf = Hb + wid*(2*WBUF);
    float* Gmy   = Gs + kh*(Bsz*GS);

    // prologue: fragment-paired tf32 weights (pair = k elems {kk+tg, kk+tg+4})
    for (int idx = tid; idx < GR*512; idx += 512){
        int r = idx>>9, p = idx&511;
        int k0 = (p>>2)<<3, tp = p&3;
        int gt = r>>3, u = r&7;
        const float* w = whh + ((size_t)(gt*Hsz + bx*UPC + u))*Hsz;
        Wp[r*WST2 + (p>>2)*4 + tp] = make_float2(tf32f(w[k0+tp]), tf32f(w[k0+tp+4]));
    }
    if (tid < GR){ int gt=tid>>3, u=tid&7; bh[tid] = bhh[gt*Hsz + bx*UPC + u]; }
    __syncthreads();

    const int eu = tid&7, eb0 = (tid>>3)*2;   // epilogue: unit, 2 batch rows
    const int ucol = bx*UPC + eu;
    const float br = bh[eu], bz = bh[UPC+eu], bn = bh[2*UPC+eu];
    float hprev[2] = {0.f, 0.f};              // register-carried own h_old

    for (int t=0; t<Tsz; ++t){
        const float* hb = hs + (size_t)(t-1)*BH;   // deref'd only when t>0

        // prefetch epilogue xi inputs (latency hides under mma phase)
        float pxr[2], pxz[2], pxn[2];
        #pragma unroll
        for (int i=0;i<2;++i){
            int b = eb0 + i;
            const float* xb = xi + ((size_t)t*Bsz + b)*G3sz + bx*UPC + eu;
            pxr[i]=xb[0]; pxz[i]=xb[Hsz]; pxn[i]=xb[2*Hsz];
        }

        if (t>0){
            float C[3][4] = {};
            stage2(hb, m0, kbase, mybuf, lane);
            for (int c=0; c<NCH; ++c){
                if (c+1 < NCH){
                    stage2(hb, m0, kbase + (c+1)*CH, mybuf + ((c+1)&1)*WBUF, lane);
                    asm volatile("cp.async.wait_group 1;" ::: "memory");
                } else {
                    asm volatile("cp.async.wait_group 0;" ::: "memory");
                }
                __syncwarp();
                const float* war = mybuf + (c&1)*WBUF + g*HST2 + tg;
                const int kp0 = ((kbase + c*CH)>>3)*4 + tg;
                #pragma unroll
                for (int kk=0; kk<CH; kk+=8){
                    unsigned a[4];
                    a[0]=tf32u(war[kk]);      a[1]=tf32u(war[8*HST2+kk]);
                    a[2]=tf32u(war[kk+4]);    a[3]=tf32u(war[8*HST2+kk+4]);
                    const int kp = kp0 + (kk>>3)*4;
                    #pragma unroll
                    for (int nt=0; nt<3; ++nt){
                        float2 bp = Wp[(nt*8+g)*WST2 + kp];
                        mma8(C[nt], a, __float_as_uint(bp.x), __float_as_uint(bp.y));
                    }
                }
            }
            #pragma unroll
            for (int nt=0; nt<3; ++nt){
                int row = m0+g, col = nt*8+2*tg;
                *(float2*)&Gmy[row*GS+col]     = make_float2(C[nt][0], C[nt][1]);
                *(float2*)&Gmy[(row+8)*GS+col] = make_float2(C[nt][2], C[nt][3]);
            }
        }
        __syncthreads();

        // epilogue: 2 (b,u) pairs per thread; sum the two split-K partials
        #pragma unroll
        for (int i=0; i<2; ++i){
            int b = eb0 + i;
            float Gr=0.f, Gz=0.f, Gn=0.f;
            if (t>0){
                Gr = Gs[b*GS+eu]       + Gs[Bsz*GS + b*GS+eu];
                Gz = Gs[b*GS+UPC+eu]   + Gs[Bsz*GS + b*GS+UPC+eu];
                Gn = Gs[b*GS+2*UPC+eu] + Gs[Bsz*GS + b*GS+2*UPC+eu];
            }
            float r  = fast_sigmoid(pxr[i] + Gr + br);
            float z  = fast_sigmoid(pxz[i] + Gz + bz);
            float nn = fast_tanh(pxn[i] + r*(Gn + bn));
            float hn = (1.f - z)*nn + z*hprev[i];
            hprev[i] = hn;
            hs[((size_t)t*Bsz + b)*Hsz + ucol] = hn;
        }

        if (t < Tsz-1){
            __threadfence();
            grid_barrier();
        }
    }
}

// ---------------- 3) FC: out[b][p] = h_last[b] . fc_w[p] + fc_b[p] ----------------
__global__ void k_fc(const float* __restrict__ fw, const float* __restrict__ fb,
                     float* __restrict__ out)
{
    __shared__ float w[Hsz];
    const int p = blockIdx.x, b = threadIdx.x;
    for (int k=b; k<Hsz; k+=Bsz) w[k] = fw[(size_t)p*Hsz + k];
    __syncthreads();
    const float* h = g_hsA + ((size_t)(Tsz-1)*Bsz + b)*Hsz;
    float s = 0.f;
    #pragma unroll 8
    for (int k=0; k<Hsz; ++k) s += h[k]*w[k];
    out[b*PREDsz + p] = s + fb[p];
}

// ---------------- launch ----------------
extern "C" void kernel_launch(void* const* d_in, const int* in_sizes, int n_in,
                              void* d_out, int out_size)
{
    const float* x    = (const float*)d_in[0];
    const float* wih0 = (const float*)d_in[1];
    const float* whh0 = (const float*)d_in[2];
    const float* bih0 = (const float*)d_in[3];
    const float* bhh0 = (const float*)d_in[4];
    const float* wih1 = (const float*)d_in[5];
    const float* whh1 = (const float*)d_in[6];
    const float* bih1 = (const float*)d_in[7];
    const float* bhh1 = (const float*)d_in[8];
    const float* wih2 = (const float*)d_in[9];
    const float* whh2 = (const float*)d_in[10];
    const float* bih2 = (const float*)d_in[11];
    const float* bhh2 = (const float*)d_in[12];
    const float* fcw  = (const float*)d_in[13];
    const float* fcb  = (const float*)d_in[14];
    float* out = (float*)d_out;

    cudaFuncSetAttribute(k_scan, cudaFuncAttributeMaxDynamicSharedMemorySize, SCAN_SMEM_BYTES);
    cudaFuncSetAttribute(k_gemm, cudaFuncAttributeMaxDynamicSharedMemorySize, GEMM_SMEM_BYTES);

    dim3 gg(G3sz/128, MR/128);   // n fastest for L2 reuse

    // layer 0 (input x, permuted [B,T,IN] -> row t*B+b)
    k_gemm<<<gg, 256, GEMM_SMEM_BYTES>>>(x, 0, wih0, bih0, INsz, 1);
    k_scan<<<NCTA, 512, SCAN_SMEM_BYTES>>>(whh0, bhh0, 1);
    // layer 1
    k_gemm<<<gg, 256, GEMM_SMEM_BYTES>>>(nullptr, 1, wih1, bih1, Hsz, 0);
    k_scan<<<NCTA, 512, SCAN_SMEM_BYTES>>>(whh1, bhh1, 2);
    // layer 2
    k_gemm<<<gg, 256, GEMM_SMEM_BYTES>>>(nullptr, 2, wih2, bih2, Hsz, 0);
    k_scan<<<NCTA, 512, SCAN_SMEM_BYTES>>>(whh2, bhh2, 1);
    // head
    k_fc<<<PREDsz, Bsz>>>(fcw, fcb, out);
}

// round 14
// speedup vs baseline: 1.6609x; 1.0018x over previous
#include <cuda_runtime.h>
#include <cuda_bf16.h>
#include <cstdint>

// Problem dims
#define Bsz   128
#define Tsz   512
#define INsz  128
#define Hsz   1024
#define G3sz  3072
#define PREDsz 96
#define MR    (Tsz*Bsz)        // 65536 rows
#define BH    (Bsz*Hsz)        // 131072

// Scan kernel config: 128 CTAs, 8 units each, 16 warps (split-K 2), depth-4 ring
#define NCTA  128
#define UPC   8                // units per CTA
#define GR    (3*UPC)          // gate rows per CTA = 24
#define WST2  516              // Wp row stride in float2 (conflict-free LDS.64)
#define GS    26               // Gs row stride (floats)
#define CH    16               // staging chunk columns
#define NCH   32               // chunks per K-half (512/16)
#define NBUF  4                // ring depth (prefetch distance 3)
#define HST2  20               // staging row stride: (20g+tg) all distinct mod 32
#define WBUF  (16*HST2)        // 320 floats: one 16-row staging buffer
#define OFF_BH   (GR*WST2*2)                     // 24768
#define OFF_GS   (OFF_BH + 32)                   // 24800
#define OFF_HB   (OFF_GS + 2*Bsz*GS)             // 31456
#define SCAN_SMEM_FLOATS (OFF_HB + 16*NBUF*WBUF) // 51936
#define SCAN_SMEM_BYTES  (SCAN_SMEM_FLOATS*4)    // 207744 B

// ---------------- device scratch (allocation-free rule) ----------------
__device__ float g_xi [(size_t)MR*G3sz];   // [T,B,3H] input-side gate projections
__device__ float g_hsA[(size_t)MR*Hsz];    // [T,B,H] hidden sequence buffer A
__device__ float g_hsB[(size_t)MR*Hsz];    // [T,B,H] hidden sequence buffer B
__device__ unsigned g_cnt = 0;             // one-sided barrier counter (monotonic)

// ---------------- helpers ----------------
__device__ __forceinline__ unsigned tf32u(float f){
    unsigned u; asm("cvt.rna.tf32.f32 %0, %1;" : "=r"(u) : "f"(f));
    return u;
}
__device__ __forceinline__ float tf32f(float f){ return __uint_as_float(tf32u(f)); }

__device__ __forceinline__ void mma8(float* d, const unsigned* a, unsigned b0, unsigned b1){
    asm volatile("mma.sync.aligned.m16n8k8.row.col.f32.tf32.tf32.f32 "
        "{%0,%1,%2,%3},{%4,%5,%6,%7},{%8,%9},{%0,%1,%2,%3};"
        : "+f"(d[0]),"+f"(d[1]),"+f"(d[2]),"+f"(d[3])
        : "r"(a[0]),"r"(a[1]),"r"(a[2]),"r"(a[3]),"r"(b0),"r"(b1));
}

__device__ __forceinline__ float fast_sigmoid(float x){
    return 1.f/(1.f + __expf(-x));
}
__device__ __forceinline__ float fast_tanh(float x){
    float ax = fabsf(x);
    float e  = __expf(2.f*ax);
    float th = 1.f - 2.f/(e + 1.f);
    return copysignf(th, x);
}

// ---------------- 1) XI = A @ W^T + bias  (round-7 proven GEMM) ----------------
__global__ void __launch_bounds__(256) k_gemm(const float* __restrict__ ext, int sel,
        const float* __restrict__ W, const float* __restrict__ bias,
        int K, int perm)
{
    __shared__ float As[2][128][20];
    __shared__ float Bs[2][128][20];

    const float* A = ext ? ext : (sel==1 ? g_hsA : g_hsB);

    const int tid = threadIdx.x;
    const int lane = tid&31, wid = tid>>5;
    const int g = lane>>2, tg = lane&3;
    const int wm = wid&3, wn = wid>>2;           // 4 x 2 warps, warp tile 32x64
    const int n0 = blockIdx.x*128, m0 = blockIdx.y*128;
    const int r0 = tid>>2, q0 = tid&3;

    int ra = m0 + r0, rb = m0 + r0 + 64;
    const float* Arow0 = (perm ? A + (((size_t)(ra&(Bsz-1)))*Tsz + (ra>>7))*K
                               : A + (size_t)ra*K) + q0*4;
    const float* Arow1 = (perm ? A + (((size_t)(rb&(Bsz-1)))*Tsz + (rb>>7))*K
                               : A + (size_t)rb*K) + q0*4;
    const float* Wrow0 = W + (size_t)(n0+r0   )*K + q0*4;
    const float* Wrow1 = W + (size_t)(n0+r0+64)*K + q0*4;

    float C[2][8][4] = {};

    {   // prologue: tile 0 -> buffer 0
        float4 a0=*(const float4*)Arow0, a1=*(const float4*)Arow1;
        float4 b0=*(const float4*)Wrow0, b1=*(const float4*)Wrow1;
        float* p;
        p=&As[0][r0   ][q0*4]; p[0]=tf32f(a0.x);p[1]=tf32f(a0.y);p[2]=tf32f(a0.z);p[3]=tf32f(a0.w);
        p=&As[0][r0+64][q0*4]; p[0]=tf32f(a1.x);p[1]=tf32f(a1.y);p[2]=tf32f(a1.z);p[3]=tf32f(a1.w);
        p=&Bs[0][r0   ][q0*4]; p[0]=tf32f(b0.x);p[1]=tf32f(b0.y);p[2]=tf32f(b0.z);p[3]=tf32f(b0.w);
        p=&Bs[0][r0+64][q0*4]; p[0]=tf32f(b1.x);p[1]=tf32f(b1.y);p[2]=tf32f(b1.z);p[3]=tf32f(b1.w);
    }
    __syncthreads();

    const int nkb = K>>4;
    float4 na0,na1,nb0,nb1;
    for (int kb=0; kb<nkb; ++kb){
        if (kb+1<nkb){
            int k0=(kb+1)<<4;
            na0=*(const float4*)(Arow0+k0); na1=*(const float4*)(Arow1+k0);
            nb0=*(const float4*)(Wrow0+k0); nb1=*(const float4*)(Wrow1+k0);
        }
        const int cur = kb&1;
        #pragma unroll
        for (int ks=0; ks<2; ++ks){
            const int kk = ks*8;
            unsigned a[2][4];
            #pragma unroll
            for (int mt=0; mt<2; ++mt){
                int row = wm*32+mt*16;
                a[mt][0]=__float_as_uint(As[cur][row+g  ][kk+tg  ]);
                a[mt][1]=__float_as_uint(As[cur][row+g+8][kk+tg  ]);
                a[mt][2]=__float_as_uint(As[cur][row+g  ][kk+tg+4]);
                a[mt][3]=__float_as_uint(As[cur][row+g+8][kk+tg+4]);
            }
            #pragma unroll
            for (int nt=0; nt<8; ++nt){
                int col = wn*64+nt*8+g;
                unsigned b0=__float_as_uint(Bs[cur][col][kk+tg  ]);
                unsigned b1=__float_as_uint(Bs[cur][col][kk+tg+4]);
                mma8(C[0][nt], a[0], b0, b1);
                mma8(C[1][nt], a[1], b0, b1);
            }
        }
        if (kb+1<nkb){
            const int nb=(kb+1)&1;
            float* p;
            p=&As[nb][r0   ][q0*4]; p[0]=tf32f(na0.x);p[1]=tf32f(na0.y);p[2]=tf32f(na0.z);p[3]=tf32f(na0.w);
            p=&As[nb][r0+64][q0*4]; p[0]=tf32f(na1.x);p[1]=tf32f(na1.y);p[2]=tf32f(na1.z);p[3]=tf32f(na1.w);
            p=&Bs[nb][r0   ][q0*4]; p[0]=tf32f(nb0.x);p[1]=tf32f(nb0.y);p[2]=tf32f(nb0.z);p[3]=tf32f(nb0.w);
            p=&Bs[nb][r0+64][q0*4]; p[0]=tf32f(nb1.x);p[1]=tf32f(nb1.y);p[2]=tf32f(nb1.z);p[3]=tf32f(nb1.w);
            __syncthreads();
        }
    }

    #pragma unroll
    for (int mt=0; mt<2; ++mt){
        #pragma unroll
        for (int nt=0; nt<8; ++nt){
            int row = m0 + wm*32 + mt*16 + g;
            int col = n0 + wn*64 + nt*8 + 2*tg;
            float bb0 = bias[col], bb1 = bias[col+1];
            float2 v;
            v.x = C[mt][nt][0]+bb0; v.y = C[mt][nt][1]+bb1;
            *(float2*)&g_xi[(size_t)row*G3sz+col] = v;
            v.x = C[mt][nt][2]+bb0; v.y = C[mt][nt][3]+bb1;
            *(float2*)&g_xi[(size_t)(row+8)*G3sz+col] = v;
        }
    }
}

// ---------------- 2) persistent GRU scan v9: depth-4 ring + counter barrier ----------------
__device__ __forceinline__ void stage2(const float* __restrict__ hb, int m0, int kg0,
                                       float* buf, int lane){
    #pragma unroll
    for (int j=0;j<2;++j){
        int idx = lane + j*32;          // 0..63 : 16 rows x 4 segs(16B)
        int row = idx>>2, c4 = idx&3;
        const float* src = hb + (size_t)(m0+row)*Hsz + kg0 + c4*4;
        unsigned dst = (unsigned)__cvta_generic_to_shared(buf + row*HST2 + c4*4);
        asm volatile("cp.async.cg.shared.global [%0], [%1], 16;" :: "r"(dst), "l"(src));
    }
    asm volatile("cp.async.commit_group;" ::: "memory");
}

__global__ void __launch_bounds__(512) k_scan(const float* __restrict__ whh,
        const float* __restrict__ bhh, int sel)
{
    extern __shared__ float sm[];
    float2* Wp = (float2*)sm;              // [GR][WST2] fragment-paired tf32 w_hh
    float*  bh = sm + OFF_BH;              // [GR] biases
    float*  Gs = sm + OFF_GS;              // [2][128][GS] split-K partial gates
    float*  Hb = sm + OFF_HB;              // [16][NBUF][WBUF] per-warp staging rings
    __shared__ unsigned s_base;

    float* hs = (sel==1) ? g_hsA : g_hsB;
    const float* xi = g_xi;

    const int tid = threadIdx.x, bx = blockIdx.x;
    const int lane = tid&31, wid = tid>>5;
    const int g = lane>>2, tg = lane&3;
    const int kh = wid&1, mg = wid>>1;     // K-half, m-group
    const int m0 = mg*16;
    const int kbase = kh*512;
    float* mybuf = Hb + wid*(NBUF*WBUF);
    float* Gmy   = Gs + kh*(Bsz*GS);

    if (tid==0) s_base = *(volatile unsigned*)&g_cnt;

    // prologue: fragment-paired tf32 weights (pair = k elems {kk+tg, kk+tg+4})
    for (int idx = tid; idx < GR*512; idx += 512){
        int r = idx>>9, p = idx&511;
        int k0 = (p>>2)<<3, tp = p&3;
        int gt = r>>3, u = r&7;
        const float* w = whh + ((size_t)(gt*Hsz + bx*UPC + u))*Hsz;
        Wp[r*WST2 + (p>>2)*4 + tp] = make_float2(tf32f(w[k0+tp]), tf32f(w[k0+tp+4]));
    }
    if (tid < GR){ int gt=tid>>3, u=tid&7; bh[tid] = bhh[gt*Hsz + bx*UPC + u]; }
    __syncthreads();
    const unsigned rbase = s_base;

    const int eu = tid&7, eb0 = (tid>>3)*2;   // epilogue: unit, 2 batch rows
    const int ucol = bx*UPC + eu;
    const float br = bh[eu], bz = bh[UPC+eu], bn = bh[2*UPC+eu];
    float hprev[2] = {0.f, 0.f};              // register-carried own h_old

    for (int t=0; t<Tsz; ++t){
        const float* hb = hs + (size_t)(t-1)*BH;   // deref'd only when t>0

        // prefetch epilogue xi inputs (latency hides under mma phase)
        float pxr[2], pxz[2], pxn[2];
        #pragma unroll
        for (int i=0;i<2;++i){
            int b = eb0 + i;
            const float* xb = xi + ((size_t)t*Bsz + b)*G3sz + bx*UPC + eu;
            pxr[i]=xb[0]; pxz[i]=xb[Hsz]; pxn[i]=xb[2*Hsz];
        }

        if (t>0){
            float C[3][4] = {};
            stage2(hb, m0, kbase,        mybuf,          lane);
            stage2(hb, m0, kbase+CH,     mybuf +   WBUF, lane);
            stage2(hb, m0, kbase+2*CH,   mybuf + 2*WBUF, lane);
            for (int c=0; c<NCH; ++c){
                if (c+3 < NCH){
                    stage2(hb, m0, kbase + (c+3)*CH, mybuf + ((c+3)&3)*WBUF, lane);
                    asm volatile("cp.async.wait_group 3;" ::: "memory");
                } else if (c+2 < NCH){
                    asm volatile("cp.async.wait_group 2;" ::: "memory");
                } else if (c+1 < NCH){
                    asm volatile("cp.async.wait_group 1;" ::: "memory");
                } else {
                    asm volatile("cp.async.wait_group 0;" ::: "memory");
                }
                __syncwarp();
                const float* war = mybuf + (c&3)*WBUF + g*HST2 + tg;
                const int kp0 = ((kbase + c*CH)>>3)*4 + tg;
                #pragma unroll
                for (int kk=0; kk<CH; kk+=8){
                    unsigned a[4];
                    a[0]=tf32u(war[kk]);      a[1]=tf32u(war[8*HST2+kk]);
                    a[2]=tf32u(war[kk+4]);    a[3]=tf32u(war[8*HST2+kk+4]);
                    const int kp = kp0 + (kk>>3)*4;
                    #pragma unroll
                    for (int nt=0; nt<3; ++nt){
                        float2 bp = Wp[(nt*8+g)*WST2 + kp];
                        mma8(C[nt], a, __float_as_uint(bp.x), __float_as_uint(bp.y));
                    }
                }
            }
            #pragma unroll
            for (int nt=0; nt<3; ++nt){
                int row = m0+g, col = nt*8+2*tg;
                *(float2*)&Gmy[row*GS+col]     = make_float2(C[nt][0], C[nt][1]);
                *(float2*)&Gmy[(row+8)*GS+col] = make_float2(C[nt][2], C[nt][3]);
            }
        }
        __syncthreads();

        // epilogue: 2 (b,u) pairs per thread; sum the two split-K partials
        #pragma unroll
        for (int i=0; i<2; ++i){
            int b = eb0 + i;
            float Gr=0.f, Gz=0.f, Gn=0.f;
            if (t>0){
                Gr = Gs[b*GS+eu]       + Gs[Bsz*GS + b*GS+eu];
                Gz = Gs[b*GS+UPC+eu]   + Gs[Bsz*GS + b*GS+UPC+eu];
                Gn = Gs[b*GS+2*UPC+eu] + Gs[Bsz*GS + b*GS+2*UPC+eu];
            }
            float r  = fast_sigmoid(pxr[i] + Gr + br);
            float z  = fast_sigmoid(pxz[i] + Gz + bz);
            float nn = fast_tanh(pxn[i] + r*(Gn + bn));
            float hn = (1.f - z)*nn + z*hprev[i];
            hprev[i] = hn;
            hs[((size_t)t*Bsz + b)*Hsz + ucol] = hn;
        }

        if (t < Tsz-1){
            // one-sided counter barrier: arrivals ARE the release
            __threadfence();
            __syncthreads();
            if (tid==0){
                atomicAdd(&g_cnt, 1u);
                unsigned tgt = rbase + (unsigned)NCTA*(unsigned)(t+1);
                while ((int)(*(volatile unsigned*)&g_cnt - tgt) < 0) __nanosleep(32);
                __threadfence();
            }
            __syncthreads();
        }
    }
}

// ---------------- 3) FC: out[b][p] = h_last[b] . fc_w[p] + fc_b[p] ----------------
__global__ void k_fc(const float* __restrict__ fw, const float* __restrict__ fb,
                     float* __restrict__ out)
{
    __shared__ float w[Hsz];
    const int p = blockIdx.x, b = threadIdx.x;
    for (int k=b; k<Hsz; k+=Bsz) w[k] = fw[(size_t)p*Hsz + k];
    __syncthreads();
    const float* h = g_hsA + ((size_t)(Tsz-1)*Bsz + b)*Hsz;
    float s = 0.f;
    #pragma unroll 8
    for (int k=0; k<Hsz; ++k) s += h[k]*w[k];
    out[b*PREDsz + p] = s + fb[p];
}

// ---------------- launch ----------------
extern "C" void kernel_launch(void* const* d_in, const int* in_sizes, int n_in,
                              void* d_out, int out_size)
{
    const float* x    = (const float*)d_in[0];
    const float* wih0 = (const float*)d_in[1];
    const float* whh0 = (const float*)d_in[2];
    const float* bih0 = (const float*)d_in[3];
    const float* bhh0 = (const float*)d_in[4];
    const float* wih1 = (const float*)d_in[5];
    const float* whh1 = (const float*)d_in[6];
    const float* bih1 = (const float*)d_in[7];
    const float* bhh1 = (const float*)d_in[8];
    const float* wih2 = (const float*)d_in[9];
    const float* whh2 = (const float*)d_in[10];
    const float* bih2 = (const float*)d_in[11];
    const float* bhh2 = (const float*)d_in[12];
    const float* fcw  = (const float*)d_in[13];
    const float* fcb  = (const float*)d_in[14];
    float* out = (float*)d_out;

    cudaFuncSetAttribute(k_scan, cudaFuncAttributeMaxDynamicSharedMemorySize, SCAN_SMEM_BYTES);

    dim3 gg(G3sz/128, MR/128);   // n fastest for L2 reuse

    // layer 0 (input x, permuted [B,T,IN] -> row t*B+b)
    k_gemm<<<gg, 256>>>(x, 0, wih0, bih0, INsz, 1);
    k_scan<<<NCTA, 512, SCAN_SMEM_BYTES>>>(whh0, bhh0, 1);
    // layer 1
    k_gemm<<<gg, 256>>>(nullptr, 1, wih1, bih1, Hsz, 0);
    k_scan<<<NCTA, 512, SCAN_SMEM_BYTES>>>(whh1, bhh1, 2);
    // layer 2
    k_gemm<<<gg, 256>>>(nullptr, 2, wih2, bih2, Hsz, 0);
    k_scan<<<NCTA, 512, SCAN_SMEM_BYTES>>>(whh2, bhh2, 1);
    // head
    k_fc<<<PREDsz, Bsz>>>(fcw, fcb, out);
}